// round 5
// baseline (speedup 1.0000x reference)
#include <cuda_runtime.h>
#include <cstdint>

#define B_TOTAL 65536
#define HDIM    256
#define GATE3   768

// ping-pong hidden-state buffers (allocation-free scratch)
__device__ float g_h[2ULL * B_TOTAL * HDIM];

#define A_STRIDE 260                 // 128x256 A tile, padded stride (bank-safe)
#define W_STRIDE 72                  // 16x64 weight tile, padded stride (bank-safe)
#define SMEM_WORDS (128 * A_STRIDE + 3 * 2 * 16 * W_STRIDE)
#define SMEM_BYTES (SMEM_WORDS * 4)

__device__ __forceinline__ unsigned f2tf(float f) {
    unsigned u;
    asm("cvt.rna.tf32.f32 %0, %1;" : "=r"(u) : "f"(f));
    return u;
}

__device__ __forceinline__ void mma_tf32(float c[4],
                                         unsigned a0, unsigned a1, unsigned a2, unsigned a3,
                                         unsigned b0, unsigned b1) {
    asm volatile(
        "mma.sync.aligned.m16n8k8.row.col.f32.tf32.tf32.f32 "
        "{%0,%1,%2,%3}, {%4,%5,%6,%7}, {%8,%9}, {%0,%1,%2,%3};\n"
        : "+f"(c[0]), "+f"(c[1]), "+f"(c[2]), "+f"(c[3])
        : "r"(a0), "r"(a1), "r"(a2), "r"(a3), "r"(b0), "r"(b1));
}

// One GRU cell:  h_out = (1-z)*n + z*h_prev  fully fused.
// Grid: (4 h-col chunks of 64, 512 batch tiles of 128). 512 threads.
// Accumulators per CTA: r, z, i_n, h_n  each [128 x 64] fp32 in registers.
// K runs over [x (256) | h (256)]; phase 0 feeds r,z,i_n; phase 1 feeds r,z,h_n.
__global__ void __launch_bounds__(512, 1)
gru_unit(const float* __restrict__ x, const float* __restrict__ hprev,
         float* __restrict__ hout,
         const float* __restrict__ Wih, const float* __restrict__ Whh,
         const float* __restrict__ bih, const float* __restrict__ bhh) {
    extern __shared__ unsigned smem[];
    unsigned* As = smem;                       // [128][A_STRIDE] (tf32 bits)
    unsigned* Ws = smem + 128 * A_STRIDE;      // [3 acc][2 buf][16 k][W_STRIDE]

    const int tid  = threadIdx.x;
    const int lane = tid & 31;
    const int wid  = tid >> 5;
    const int grp  = lane >> 2;    // 0..7
    const int tg   = lane & 3;     // 0..3
    const int wm   = wid >> 1;     // 0..7  (rows 16*wm)
    const int wn   = wid & 1;      // 0..1  (cols 32*wn)
    const int j0   = blockIdx.x * 64;
    const int b0   = blockIdx.y * 128;

    float C[4][4][4];              // [r,z,n_i,n_h][ntile][cfrag]
#pragma unroll
    for (int a = 0; a < 4; a++)
#pragma unroll
        for (int t = 0; t < 4; t++)
#pragma unroll
            for (int c = 0; c < 4; c++) C[a][t][c] = 0.f;

    for (int phase = 0; phase < 2; phase++) {
        const float* Asrc = phase ? hprev : x;
        const float* Wsrc = phase ? Whh : Wih;

        __syncthreads();   // previous phase fully done with As / Ws

        // ---- stage A tile: 128 rows x 256 cols, rna-rounded to tf32 ----
        {
            const float4* src4 = reinterpret_cast<const float4*>(Asrc + (size_t)b0 * 256);
#pragma unroll
            for (int i = 0; i < 16; i++) {
                int idx = tid + i * 512;       // 0..8191
                int row = idx >> 6;
                int q   = idx & 63;
                float4 v = src4[row * 64 + q];
                uint4 u;
                u.x = f2tf(v.x); u.y = f2tf(v.y); u.z = f2tf(v.z); u.w = f2tf(v.w);
                *reinterpret_cast<uint4*>(&As[row * A_STRIDE + 4 * q]) = u;
            }
        }

        // ---- weight tile LDG helper (3 tiles of [64 j][16 k], float4 per thread) ----
        uint4 wcur[2], wnxt[2];
        auto ldgW = [&](int s, uint4 wr[2]) {
#pragma unroll
            for (int i = 0; i < 2; i++) {
                int idx = tid + i * 512;
                if (idx < 768) {
                    int a   = idx >> 8;         // accumulator/gate 0..2
                    int rq  = idx & 255;
                    int r64 = rq >> 2;          // j within chunk
                    int q   = rq & 3;           // k quad
                    const float* gp = Wsrc + (size_t)(a * 256 + j0 + r64) * 256 + s * 16 + q * 4;
                    float4 v = *reinterpret_cast<const float4*>(gp);
                    wr[i].x = f2tf(v.x); wr[i].y = f2tf(v.y);
                    wr[i].z = f2tf(v.z); wr[i].w = f2tf(v.w);
                }
            }
        };
        auto stsW = [&](int buf, uint4 wr[2]) {
#pragma unroll
            for (int i = 0; i < 2; i++) {
                int idx = tid + i * 512;
                if (idx < 768) {
                    int a   = idx >> 8;
                    int rq  = idx & 255;
                    int r64 = rq >> 2;
                    int q   = rq & 3;
                    unsigned* wb = Ws + (size_t)((a * 2 + buf) * 16) * W_STRIDE;
                    wb[(q * 4 + 0) * W_STRIDE + r64] = wr[i].x;
                    wb[(q * 4 + 1) * W_STRIDE + r64] = wr[i].y;
                    wb[(q * 4 + 2) * W_STRIDE + r64] = wr[i].z;
                    wb[(q * 4 + 3) * W_STRIDE + r64] = wr[i].w;
                }
            }
        };

        ldgW(0, wcur);
        __syncthreads();   // A tile visible to all warps
        stsW(0, wcur);
        __syncthreads();   // weight buf 0 visible

        for (int s = 0; s < 16; s++) {
            if (s < 15) ldgW(s + 1, wnxt);
#pragma unroll
            for (int half = 0; half < 2; half++) {
                const int kc = s * 16 + half * 8 + tg;
                unsigned a0 = As[(16 * wm + grp)     * A_STRIDE + kc];
                unsigned a1 = As[(16 * wm + grp + 8) * A_STRIDE + kc];
                unsigned a2 = As[(16 * wm + grp)     * A_STRIDE + kc + 4];
                unsigned a3 = As[(16 * wm + grp + 8) * A_STRIDE + kc + 4];
#pragma unroll
                for (int acc = 0; acc < 3; acc++) {
                    const int ai = (acc == 2) ? (2 + phase) : acc;
                    const unsigned* wb = Ws + (size_t)((acc * 2 + (s & 1)) * 16 + half * 8) * W_STRIDE;
#pragma unroll
                    for (int t = 0; t < 4; t++) {
                        int n = wn * 32 + t * 8 + grp;
                        unsigned bb0 = wb[tg * W_STRIDE + n];
                        unsigned bb1 = wb[(tg + 4) * W_STRIDE + n];
                        mma_tf32(C[ai][t], a0, a1, a2, a3, bb0, bb1);
                    }
                }
            }
            // Single barrier per step: writes below target buffer (s+1)&1,
            // whose last readers were fenced by the PREVIOUS iteration's
            // barrier, so no WAR hazard; this barrier covers both
            // "reads of buf s&1 done" and "writes of buf (s+1)&1 visible".
            if (s < 15) stsW((s + 1) & 1, wnxt);
            __syncthreads();
        }
    }

    // ---- fused gate epilogue (exact fp32 h_prev) ----
    const int mrow = b0 + 16 * wm + grp;
#pragma unroll
    for (int t = 0; t < 4; t++) {
        int col0 = j0 + wn * 32 + t * 8 + 2 * tg;
#pragma unroll
        for (int cc = 0; cc < 2; cc++) {
            int j = col0 + cc;
            float br  = bih[j]       + bhh[j];
            float bz  = bih[256 + j] + bhh[256 + j];
            float bni = bih[512 + j];
            float bnh = bhh[512 + j];
#pragma unroll
            for (int rr = 0; rr < 2; rr++) {
                int row = mrow + rr * 8;
                int ci  = rr * 2 + cc;
                float vr = C[0][t][ci] + br;
                float vz = C[1][t][ci] + bz;
                float n1 = C[2][t][ci] + bni;
                float n2 = C[3][t][ci] + bnh;
                float r  = 1.f / (1.f + __expf(-vr));
                float z  = 1.f / (1.f + __expf(-vz));
                float n  = tanhf(n1 + r * n2);
                float hp = hprev[(size_t)row * 256 + j];
                hout[(size_t)row * 256 + j] = (1.f - z) * n + z * hp;
            }
        }
    }
}

__global__ void init_h(const float* __restrict__ h0, float* __restrict__ dst) {
    size_t total = (size_t)B_TOTAL * HDIM;
    for (size_t k = blockIdx.x * (size_t)blockDim.x + threadIdx.x; k < total;
         k += (size_t)gridDim.x * blockDim.x)
        dst[k] = h0[k & 255];
}

extern "C" void kernel_launch(void* const* d_in, const int* in_sizes, int n_in,
                              void* d_out, int out_size) {
    const float* x   = (const float*)d_in[0];
    const float* Wih = (const float*)d_in[1];
    const float* Whh = (const float*)d_in[2];
    const float* bih = (const float*)d_in[3];
    const float* bhh = (const float*)d_in[4];
    const float* h0  = (const float*)d_in[5];
    float* out = (float*)d_out;

    float* hb = nullptr;
    cudaGetSymbolAddress((void**)&hb, g_h);
    float* hbuf0 = hb;
    float* hbuf1 = hb + (size_t)B_TOTAL * HDIM;

    cudaFuncSetAttribute(gru_unit, cudaFuncAttributeMaxDynamicSharedMemorySize, SMEM_BYTES);

    init_h<<<512, 256>>>(h0, hbuf0);

    for (int u = 0; u < 8; u++) {
        const float* src = (u & 1) ? hbuf1 : hbuf0;
        float*       dst = (u == 7) ? out : ((u & 1) ? hbuf0 : hbuf1);
        gru_unit<<<dim3(4, 512), 512, SMEM_BYTES>>>(
            x, src, dst,
            Wih + (size_t)u * GATE3 * 256,
            Whh + (size_t)u * GATE3 * 256,
            bih + (size_t)u * GATE3,
            bhh + (size_t)u * GATE3);
    }
}

// round 8
// speedup vs baseline: 1.0970x; 1.0970x over previous
#include <cuda_runtime.h>
#include <cstdint>

#define B_TOTAL 65536
#define HDIM    256
#define GATE3   768

// ping-pong hidden-state buffers (allocation-free scratch)
__device__ float g_h[2ULL * B_TOTAL * HDIM];

#define A_STRIDE 260   // 128x256 A tile, padded stride (bank map 4*grp+tg, conflict-free)
#define W_STRIDE 72    // weight tile [16 k][64 n] padded stride (bank map 8*tg+grp, conflict-free)
#define SMEM_WORDS (128 * A_STRIDE + 3 * 2 * 16 * W_STRIDE)
#define SMEM_BYTES (SMEM_WORDS * 4)

__device__ __forceinline__ unsigned f2tf(float f) {
    unsigned u;
    asm("cvt.rna.tf32.f32 %0, %1;" : "=r"(u) : "f"(f));
    return u;
}

__device__ __forceinline__ void mma_tf32(float c[4],
                                         unsigned a0, unsigned a1, unsigned a2, unsigned a3,
                                         unsigned b0, unsigned b1) {
    asm volatile(
        "mma.sync.aligned.m16n8k8.row.col.f32.tf32.tf32.f32 "
        "{%0,%1,%2,%3}, {%4,%5,%6,%7}, {%8,%9}, {%0,%1,%2,%3};\n"
        : "+f"(c[0]), "+f"(c[1]), "+f"(c[2]), "+f"(c[3])
        : "r"(a0), "r"(a1), "r"(a2), "r"(a3), "r"(b0), "r"(b1));
}

// One GRU cell, fully fused.  Grid: (4 h-col chunks of 64, 512 batch tiles of 128).
// 512 threads = 16 warps in a 4(M) x 4(N) grid; warp tile 32m x 16n.
// Each B fragment is reused by the warp's TWO m-tiles: B smem wavefronts drop
// 384 -> 192 per CTA per k8 vs the 8x2 grid (the measured L1 bottleneck in R5).
// A tile uses the proven linear layout from R5 (stride 260, conflict-free).
__global__ void __launch_bounds__(512, 1)
gru_unit(const float* __restrict__ x, const float* __restrict__ hprev,
         float* __restrict__ hout,
         const float* __restrict__ Wih, const float* __restrict__ Whh,
         const float* __restrict__ bih, const float* __restrict__ bhh) {
    extern __shared__ unsigned smem[];
    unsigned* As = smem;                       // [128][A_STRIDE] (tf32 bits)
    unsigned* Ws = smem + 128 * A_STRIDE;      // [3 acc][2 buf][16 k][W_STRIDE]

    const int tid  = threadIdx.x;
    const int lane = tid & 31;
    const int wid  = tid >> 5;
    const int grp  = lane >> 2;    // 0..7
    const int tg   = lane & 3;     // 0..3
    const int wm   = wid & 3;      // 0..3  (rows 32*wm)
    const int wn   = wid >> 2;     // 0..3  (cols 16*wn)
    const int j0   = blockIdx.x * 64;
    const int b0   = blockIdx.y * 128;

    float C[4][2][2][4];           // [r,z,n_i,n_h][m-tile][n-tile][cfrag]
#pragma unroll
    for (int a = 0; a < 4; a++)
#pragma unroll
        for (int mt = 0; mt < 2; mt++)
#pragma unroll
            for (int t = 0; t < 2; t++)
#pragma unroll
                for (int c = 0; c < 4; c++) C[a][mt][t][c] = 0.f;

    for (int phase = 0; phase < 2; phase++) {
        const float* Asrc = phase ? hprev : x;
        const float* Wsrc = phase ? Whh : Wih;

        __syncthreads();   // previous phase fully done with As / Ws

        // ---- stage A tile: 128 rows x 256 cols, rna-rounded to tf32 ----
        {
            const float4* src4 = reinterpret_cast<const float4*>(Asrc + (size_t)b0 * 256);
#pragma unroll
            for (int i = 0; i < 16; i++) {
                int idx = tid + i * 512;       // 0..8191
                int row = idx >> 6;
                int q   = idx & 63;
                float4 v = src4[row * 64 + q];
                uint4 u;
                u.x = f2tf(v.x); u.y = f2tf(v.y); u.z = f2tf(v.z); u.w = f2tf(v.w);
                *reinterpret_cast<uint4*>(&As[row * A_STRIDE + 4 * q]) = u;
            }
        }

        // ---- weight tile LDG helper (3 tiles of [64 j][16 k], float4/thread) ----
        uint4 wcur[2], wnxt[2];
        auto ldgW = [&](int s, uint4 wr[2]) {
#pragma unroll
            for (int i = 0; i < 2; i++) {
                int idx = tid + i * 512;
                if (idx < 768) {
                    int a   = idx >> 8;         // gate 0..2
                    int rq  = idx & 255;
                    int r64 = rq >> 2;          // j within chunk
                    int q   = rq & 3;           // k quad
                    const float* gp = Wsrc + (size_t)(a * 256 + j0 + r64) * 256 + s * 16 + q * 4;
                    float4 v = *reinterpret_cast<const float4*>(gp);
                    wr[i].x = f2tf(v.x); wr[i].y = f2tf(v.y);
                    wr[i].z = f2tf(v.z); wr[i].w = f2tf(v.w);
                }
            }
        };
        auto stsW = [&](int buf, uint4 wr[2]) {
#pragma unroll
            for (int i = 0; i < 2; i++) {
                int idx = tid + i * 512;
                if (idx < 768) {
                    int a   = idx >> 8;
                    int rq  = idx & 255;
                    int r64 = rq >> 2;
                    int q   = rq & 3;
                    unsigned* wb = Ws + (size_t)((a * 2 + buf) * 16) * W_STRIDE;
                    wb[(q * 4 + 0) * W_STRIDE + r64] = wr[i].x;
                    wb[(q * 4 + 1) * W_STRIDE + r64] = wr[i].y;
                    wb[(q * 4 + 2) * W_STRIDE + r64] = wr[i].z;
                    wb[(q * 4 + 3) * W_STRIDE + r64] = wr[i].w;
                }
            }
        };

        ldgW(0, wcur);
        __syncthreads();   // A tile visible
        stsW(0, wcur);
        __syncthreads();   // weight buf 0 visible

        const int rowa0 = 32 * wm + grp;       // m-tile 0, low row
        for (int s = 0; s < 16; s++) {
            if (s < 15) ldgW(s + 1, wnxt);
#pragma unroll
            for (int gsub = 0; gsub < 2; gsub++) {
                const int kc = s * 16 + gsub * 8 + tg;
                // A fragments for both m-tiles (scalar LDS, conflict-free)
                unsigned a0[2], a1[2], a2[2], a3[2];
#pragma unroll
                for (int mt = 0; mt < 2; mt++) {
                    int r0 = rowa0 + 16 * mt;
                    a0[mt] = As[r0       * A_STRIDE + kc];
                    a1[mt] = As[(r0 + 8) * A_STRIDE + kc];
                    a2[mt] = As[r0       * A_STRIDE + kc + 4];
                    a3[mt] = As[(r0 + 8) * A_STRIDE + kc + 4];
                }
#pragma unroll
                for (int acc = 0; acc < 3; acc++) {
                    const int ai = (acc == 2) ? (2 + phase) : acc;
                    const unsigned* wb =
                        Ws + (size_t)((acc * 2 + (s & 1)) * 16 + gsub * 8) * W_STRIDE;
#pragma unroll
                    for (int t = 0; t < 2; t++) {
                        int n = wn * 16 + t * 8 + grp;
                        unsigned bb0 = wb[tg * W_STRIDE + n];
                        unsigned bb1 = wb[(tg + 4) * W_STRIDE + n];
#pragma unroll
                        for (int mt = 0; mt < 2; mt++)
                            mma_tf32(C[ai][mt][t],
                                     a0[mt], a1[mt], a2[mt], a3[mt], bb0, bb1);
                    }
                }
            }
            // Single barrier per step: stsW targets buffer (s+1)&1 whose last
            // readers were fenced by the previous iteration's barrier.
            if (s < 15) stsW((s + 1) & 1, wnxt);
            __syncthreads();
        }
    }

    // ---- fused gate epilogue (exact fp32 h_prev) ----
#pragma unroll
    for (int t = 0; t < 2; t++) {
        int col0 = j0 + wn * 16 + t * 8 + 2 * tg;
#pragma unroll
        for (int cc = 0; cc < 2; cc++) {
            int j = col0 + cc;
            float br  = bih[j]       + bhh[j];
            float bz  = bih[256 + j] + bhh[256 + j];
            float bni = bih[512 + j];
            float bnh = bhh[512 + j];
#pragma unroll
            for (int mt = 0; mt < 2; mt++) {
                int mrow = b0 + 32 * wm + 16 * mt + grp;
#pragma unroll
                for (int rr = 0; rr < 2; rr++) {
                    int row = mrow + rr * 8;
                    int ci  = rr * 2 + cc;
                    float vr = C[0][mt][t][ci] + br;
                    float vz = C[1][mt][t][ci] + bz;
                    float n1 = C[2][mt][t][ci] + bni;
                    float n2 = C[3][mt][t][ci] + bnh;
                    float r  = 1.f / (1.f + __expf(-vr));
                    float z  = 1.f / (1.f + __expf(-vz));
                    float n  = tanhf(n1 + r * n2);
                    float hp = hprev[(size_t)row * 256 + j];
                    hout[(size_t)row * 256 + j] = (1.f - z) * n + z * hp;
                }
            }
        }
    }
}

__global__ void init_h(const float* __restrict__ h0, float* __restrict__ dst) {
    size_t total = (size_t)B_TOTAL * HDIM;
    for (size_t k = blockIdx.x * (size_t)blockDim.x + threadIdx.x; k < total;
         k += (size_t)gridDim.x * blockDim.x)
        dst[k] = h0[k & 255];
}

extern "C" void kernel_launch(void* const* d_in, const int* in_sizes, int n_in,
                              void* d_out, int out_size) {
    const float* x   = (const float*)d_in[0];
    const float* Wih = (const float*)d_in[1];
    const float* Whh = (const float*)d_in[2];
    const float* bih = (const float*)d_in[3];
    const float* bhh = (const float*)d_in[4];
    const float* h0  = (const float*)d_in[5];
    float* out = (float*)d_out;

    float* hb = nullptr;
    cudaGetSymbolAddress((void**)&hb, g_h);
    float* hbuf0 = hb;
    float* hbuf1 = hb + (size_t)B_TOTAL * HDIM;

    cudaFuncSetAttribute(gru_unit, cudaFuncAttributeMaxDynamicSharedMemorySize, SMEM_BYTES);

    init_h<<<512, 256>>>(h0, hbuf0);

    for (int u = 0; u < 8; u++) {
        const float* src = (u & 1) ? hbuf1 : hbuf0;
        float*       dst = (u == 7) ? out : ((u & 1) ? hbuf0 : hbuf1);
        gru_unit<<<dim3(4, 512), 512, SMEM_BYTES>>>(
            x, src, dst,
            Wih + (size_t)u * GATE3 * 256,
            Whh + (size_t)u * GATE3 * 256,
            bih + (size_t)u * GATE3,
            bhh + (size_t)u * GATE3);
    }
}